// round 15
// baseline (speedup 1.0000x reference)
#include <cuda_runtime.h>
#include <cuda_fp16.h>
#include <math.h>
#include <stdint.h>

#define B_ 8
#define S_ 1024
#define E_ 1024
#define H_ 16
#define D_ 64
#define F_ 4096
#define TOK (B_ * S_)  // 8192

// ---------------- scratch (static device globals; no allocation) ----------------
__device__ __half g_nxh[(size_t)TOK * E_];
__device__ __half g_q  [(size_t)TOK * E_];
__device__ __half g_k  [(size_t)TOK * E_];
__device__ __half g_v  [(size_t)TOK * E_];
__device__ __half g_o  [(size_t)TOK * E_];
__device__ float  g_x1 [(size_t)TOK * E_];
__device__ __half g_nx2[(size_t)TOK * E_];
__device__ __half g_h1 [(size_t)TOK * F_];
__device__ __half g_woT[(size_t)E_ * E_];
__device__ __half g_w1T[(size_t)F_ * E_];
__device__ __half g_w2T[(size_t)E_ * F_];
__device__ __half g_wqT[(size_t)D_ * D_];
__device__ __half g_wkT[(size_t)D_ * D_];
__device__ __half g_wvT[(size_t)D_ * D_];

// ---------------- helpers ----------------
__device__ __forceinline__ void cp_async16(void* smem, const void* gmem) {
    uint32_t s = (uint32_t)__cvta_generic_to_shared(smem);
    asm volatile("cp.async.cg.shared.global [%0], [%1], 16;\n" :: "r"(s), "l"(gmem));
}
#define CP_COMMIT() asm volatile("cp.async.commit_group;\n" ::: "memory")
#define CP_WAIT0()  asm volatile("cp.async.wait_group 0;\n" ::: "memory")
#define CP_WAIT1()  asm volatile("cp.async.wait_group 1;\n" ::: "memory")
#define CP_WAIT2()  asm volatile("cp.async.wait_group 2;\n" ::: "memory")

__device__ __forceinline__ void mma_f16(float c[4], const uint32_t a[4], const uint32_t b[2]) {
    asm volatile(
        "mma.sync.aligned.m16n8k16.row.col.f32.f16.f16.f32 "
        "{%0,%1,%2,%3}, {%4,%5,%6,%7}, {%8,%9}, {%0,%1,%2,%3};\n"
        : "+f"(c[0]), "+f"(c[1]), "+f"(c[2]), "+f"(c[3])
        : "r"(a[0]), "r"(a[1]), "r"(a[2]), "r"(a[3]), "r"(b[0]), "r"(b[1]));
}
__device__ __forceinline__ uint32_t packh2(float a, float b) {
    __half2 h = __floats2half2_rn(a, b);
    return *reinterpret_cast<uint32_t*>(&h);
}
__device__ __forceinline__ void ldsm_x4_trans(uint32_t r[4], uint32_t saddr) {
    asm volatile("ldmatrix.sync.aligned.m8n8.x4.trans.shared.b16 {%0,%1,%2,%3}, [%4];"
                 : "=r"(r[0]), "=r"(r[1]), "=r"(r[2]), "=r"(r[3]) : "r"(saddr));
}

// ---------------- weight transpose + fp16 round: in [K][N] f32 -> out [N][K] f16 ----------
__global__ __launch_bounds__(256) void transpose_h_kernel(const float* __restrict__ in,
                                                          __half* __restrict__ out,
                                                          int K, int N)
{
    __shared__ float tile[32][33];
    int bx = blockIdx.x;
    int by = blockIdx.y;
    int x = bx * 32 + threadIdx.x;
    int y0 = by * 32 + threadIdx.y;
#pragma unroll
    for (int j = 0; j < 32; j += 8)
        tile[threadIdx.y + j][threadIdx.x] = in[(size_t)(y0 + j) * N + x];
    __syncthreads();
    int xo = by * 32 + threadIdx.x;
    int yo = bx * 32 + threadIdx.y;
#pragma unroll
    for (int j = 0; j < 32; j += 8)
        out[(size_t)(yo + j) * K + xo] = __float2half_rn(tile[threadIdx.x][threadIdx.y + j]);
}

// ---------------- LayerNorm: one block per row of 1024 ----------------
template <int HALFOUT>
__global__ __launch_bounds__(256) void ln_kernel(const float* __restrict__ x,
                                                 const float* __restrict__ g,
                                                 const float* __restrict__ be,
                                                 void* __restrict__ out)
{
    int row = blockIdx.x;
    int tid = threadIdx.x;
    const float4* xr = reinterpret_cast<const float4*>(x + (size_t)row * E_);
    float4 a = xr[tid];
    float s  = a.x + a.y + a.z + a.w;
    float ss = a.x * a.x + a.y * a.y + a.z * a.z + a.w * a.w;
#pragma unroll
    for (int o = 16; o > 0; o >>= 1) {
        s  += __shfl_xor_sync(0xffffffffu, s,  o);
        ss += __shfl_xor_sync(0xffffffffu, ss, o);
    }
    __shared__ float sm[8], sm2[8];
    int w = tid >> 5, lane = tid & 31;
    if (lane == 0) { sm[w] = s; sm2[w] = ss; }
    __syncthreads();
    if (tid < 32) {
        s  = (tid < 8) ? sm[tid]  : 0.f;
        ss = (tid < 8) ? sm2[tid] : 0.f;
#pragma unroll
        for (int o = 4; o > 0; o >>= 1) {
            s  += __shfl_xor_sync(0xffffffffu, s,  o);
            ss += __shfl_xor_sync(0xffffffffu, ss, o);
        }
        if (tid == 0) { sm[0] = s; sm2[0] = ss; }
    }
    __syncthreads();
    float mean = sm[0] * (1.0f / E_);
    float var  = sm2[0] * (1.0f / E_) - mean * mean;
    float inv  = rsqrtf(var + 1e-5f);
    float4 gg = reinterpret_cast<const float4*>(g)[tid];
    float4 bb = reinterpret_cast<const float4*>(be)[tid];
    float4 o4;
    o4.x = (a.x - mean) * inv * gg.x + bb.x;
    o4.y = (a.y - mean) * inv * gg.y + bb.y;
    o4.z = (a.z - mean) * inv * gg.z + bb.z;
    o4.w = (a.w - mean) * inv * gg.w + bb.w;
    if (HALFOUT) {
        __half2* op = reinterpret_cast<__half2*>((__half*)out + (size_t)row * E_ + tid * 4);
        op[0] = __floats2half2_rn(o4.x, o4.y);
        op[1] = __floats2half2_rn(o4.z, o4.w);
    } else {
        reinterpret_cast<float4*>((float*)out + (size_t)row * E_)[tid] = o4;
    }
}

// ---------------- QKV projections via fp16 mma: per (64-token tile, head, batch) --------
#define AST 72   // halves; conflict-free for fragment pattern

__global__ __launch_bounds__(128) void qkv_kernel(const __half* __restrict__ nxh,
                                                  const __half* __restrict__ wqT,
                                                  const __half* __restrict__ wkT,
                                                  const __half* __restrict__ wvT,
                                                  __half* __restrict__ q,
                                                  __half* __restrict__ k,
                                                  __half* __restrict__ v)
{
    __shared__ __half Xh[64 * AST];
    __shared__ __half Wh[64 * AST];
    int st = blockIdx.x, h = blockIdx.y, b = blockIdx.z;
    int tid  = threadIdx.x;
    int lane = tid & 31, warp = tid >> 5;
    int m0 = warp * 16;
    int r4 = lane >> 2, c4 = lane & 3;

#pragma unroll
    for (int it = 0; it < 4; it++) {
        int idx = tid + it * 128;
        int r = idx >> 3, c8 = (idx & 7) * 8;
        uint4 raw = *reinterpret_cast<const uint4*>(
            nxh + ((size_t)(b * S_ + st * 64 + r)) * E_ + h * 64 + c8);
        *reinterpret_cast<uint4*>(Xh + r * AST + c8) = raw;
    }

    const __half* Wm[3] = {wqT, wkT, wvT};
    __half*       Om[3] = {q, k, v};
    size_t obase = ((size_t)(b * H_ + h) * S_ + st * 64) * D_;

#pragma unroll 1
    for (int m = 0; m < 3; m++) {
        __syncthreads();
#pragma unroll
        for (int it = 0; it < 4; it++) {
            int idx = tid + it * 128;
            int r = idx >> 3, c8 = (idx & 7) * 8;
            uint4 raw = *reinterpret_cast<const uint4*>(Wm[m] + r * 64 + c8);
            *reinterpret_cast<uint4*>(Wh + r * AST + c8) = raw;
        }
        __syncthreads();

        float acc[8][4] = {};
#pragma unroll
        for (int ks = 0; ks < 4; ks++) {
            int kc = ks * 16;
            uint32_t a[4];
            a[0] = *reinterpret_cast<const uint32_t*>(Xh + (m0 + r4) * AST + kc + 2 * c4);
            a[1] = *reinterpret_cast<const uint32_t*>(Xh + (m0 + r4 + 8) * AST + kc + 2 * c4);
            a[2] = *reinterpret_cast<const uint32_t*>(Xh + (m0 + r4) * AST + kc + 2 * c4 + 8);
            a[3] = *reinterpret_cast<const uint32_t*>(Xh + (m0 + r4 + 8) * AST + kc + 2 * c4 + 8);
#pragma unroll
            for (int ni = 0; ni < 8; ni++) {
                int n0 = ni * 8;
                uint32_t bf[2];
                bf[0] = *reinterpret_cast<const uint32_t*>(Wh + (n0 + r4) * AST + kc + 2 * c4);
                bf[1] = *reinterpret_cast<const uint32_t*>(Wh + (n0 + r4) * AST + kc + 2 * c4 + 8);
                mma_f16(acc[ni], a, bf);
            }
        }
        __half* dst = Om[m] + obase;
#pragma unroll
        for (int ni = 0; ni < 8; ni++) {
            int cc = ni * 8 + 2 * c4;
            *reinterpret_cast<uint32_t*>(dst + (m0 + r4) * D_ + cc)     = packh2(acc[ni][0], acc[ni][1]);
            *reinterpret_cast<uint32_t*>(dst + (m0 + r4 + 8) * D_ + cc) = packh2(acc[ni][2], acc[ni][3]);
        }
    }
}

// ---------------- Causal flash attention: register softmax, ldmatrix.trans V,
//                  cp.async double-buffered K/V, heaviest-first scheduling ------------
__global__ __launch_bounds__(128) void attn_kernel(const __half* __restrict__ q,
                                                   const __half* __restrict__ k,
                                                   const __half* __restrict__ v,
                                                   __half* __restrict__ o)
{
    __shared__ __half Qh[64 * AST];
    __shared__ __half Kh[2][64 * AST];
    __shared__ __half Vh[2][64 * AST];   // row-major [s][d]

    // heaviest-first: high qt blocks launch first
    int qt = (int)gridDim.x - 1 - (int)blockIdx.x;
    int h = blockIdx.y, b = blockIdx.z;
    int tid  = threadIdx.x;
    int lane = tid & 31, warp = tid >> 5;
    int m0 = warp * 16;
    int r4 = lane >> 2, c4 = lane & 3;
    size_t head_base = (size_t)(b * H_ + h) * S_ * D_;
    const __half2 hscale = __float2half2_rn(0.03125f);  // 1/32 exact

    // ldmatrix.trans per-lane address offsets (within a V tile)
    const int lm = lane >> 3;
    const int lj = lane & 7;
    const int lrow_off = (lm & 1) * 8 + lj;
    const int lcol_off = (lm >> 1) * 8;

    // load Q (scaled)
#pragma unroll
    for (int it = 0; it < 4; it++) {
        int idx = tid + it * 128;
        int r = idx >> 3, c8 = (idx & 7) * 8;
        uint4 raw = *reinterpret_cast<const uint4*>(q + head_base + (size_t)(qt * 64 + r) * 64 + c8);
        __half2* hp = reinterpret_cast<__half2*>(&raw);
#pragma unroll
        for (int j = 0; j < 4; j++) hp[j] = __hmul2(hp[j], hscale);
        *reinterpret_cast<uint4*>(Qh + r * AST + c8) = raw;
    }

    auto stage = [&](int buf, int kt) {
#pragma unroll
        for (int it = 0; it < 4; it++) {
            int idx = tid + it * 128;
            int r = idx >> 3, c8 = (idx & 7) * 8;
            cp_async16(&Kh[buf][r * AST + c8], k + head_base + (size_t)(kt * 64 + r) * 64 + c8);
            cp_async16(&Vh[buf][r * AST + c8], v + head_base + (size_t)(kt * 64 + r) * 64 + c8);
        }
        CP_COMMIT();
    };

    float m_0 = -1e30f, m_1 = -1e30f, l_0 = 0.f, l_1 = 0.f;
    float acc_o[8][4] = {};

    stage(0, 0);

    for (int kt = 0; kt <= qt; kt++) {
        int buf = kt & 1;
        CP_WAIT0();
        __syncthreads();
        if (kt + 1 <= qt) stage(buf ^ 1, kt + 1);

        // ---- S = Q @ K^T : warp computes 16x64 in registers ----
        float s[8][4] = {};
#pragma unroll
        for (int ks = 0; ks < 4; ks++) {
            int kc = ks * 16;
            uint32_t a[4];
            a[0] = *reinterpret_cast<const uint32_t*>(Qh + (m0 + r4) * AST + kc + 2 * c4);
            a[1] = *reinterpret_cast<const uint32_t*>(Qh + (m0 + r4 + 8) * AST + kc + 2 * c4);
            a[2] = *reinterpret_cast<const uint32_t*>(Qh + (m0 + r4) * AST + kc + 2 * c4 + 8);
            a[3] = *reinterpret_cast<const uint32_t*>(Qh + (m0 + r4 + 8) * AST + kc + 2 * c4 + 8);
#pragma unroll
            for (int ni = 0; ni < 8; ni++) {
                int n0 = ni * 8;
                uint32_t bf[2];
                bf[0] = *reinterpret_cast<const uint32_t*>(&Kh[buf][(n0 + r4) * AST + kc + 2 * c4]);
                bf[1] = *reinterpret_cast<const uint32_t*>(&Kh[buf][(n0 + r4) * AST + kc + 2 * c4 + 8]);
                mma_f16(s[ni], a, bf);
            }
        }

        if (kt == qt) {
            int row0 = m0 + r4, row1 = m0 + r4 + 8;
#pragma unroll
            for (int ni = 0; ni < 8; ni++) {
                int col = ni * 8 + 2 * c4;
                if (col > row0)     s[ni][0] = -1e30f;
                if (col + 1 > row0) s[ni][1] = -1e30f;
                if (col > row1)     s[ni][2] = -1e30f;
                if (col + 1 > row1) s[ni][3] = -1e30f;
            }
        }

        // ---- register softmax ----
        float mx0 = -1e30f, mx1 = -1e30f;
#pragma unroll
        for (int ni = 0; ni < 8; ni++) {
            mx0 = fmaxf(mx0, fmaxf(s[ni][0], s[ni][1]));
            mx1 = fmaxf(mx1, fmaxf(s[ni][2], s[ni][3]));
        }
        mx0 = fmaxf(mx0, __shfl_xor_sync(0xffffffffu, mx0, 1));
        mx0 = fmaxf(mx0, __shfl_xor_sync(0xffffffffu, mx0, 2));
        mx1 = fmaxf(mx1, __shfl_xor_sync(0xffffffffu, mx1, 1));
        mx1 = fmaxf(mx1, __shfl_xor_sync(0xffffffffu, mx1, 2));

        float mn0 = fmaxf(m_0, mx0), mn1 = fmaxf(m_1, mx1);
        float corr0 = expf(m_0 - mn0), corr1 = expf(m_1 - mn1);
        float rs0 = 0.f, rs1 = 0.f;
#pragma unroll
        for (int ni = 0; ni < 8; ni++) {
            s[ni][0] = expf(s[ni][0] - mn0);
            s[ni][1] = expf(s[ni][1] - mn0);
            s[ni][2] = expf(s[ni][2] - mn1);
            s[ni][3] = expf(s[ni][3] - mn1);
            rs0 += s[ni][0] + s[ni][1];
            rs1 += s[ni][2] + s[ni][3];
        }
        rs0 += __shfl_xor_sync(0xffffffffu, rs0, 1);
        rs0 += __shfl_xor_sync(0xffffffffu, rs0, 2);
        rs1 += __shfl_xor_sync(0xffffffffu, rs1, 1);
        rs1 += __shfl_xor_sync(0xffffffffu, rs1, 2);
        l_0 = l_0 * corr0 + rs0;  m_0 = mn0;
        l_1 = l_1 * corr1 + rs1;  m_1 = mn1;

        // pack P into A-fragments (S C-frag layout == P A-frag layout)
        uint32_t pa[4][4];
#pragma unroll
        for (int kk = 0; kk < 4; kk++) {
            pa[kk][0] = packh2(s[2 * kk][0],     s[2 * kk][1]);
            pa[kk][1] = packh2(s[2 * kk][2],     s[2 * kk][3]);
            pa[kk][2] = packh2(s[2 * kk + 1][0], s[2 * kk + 1][1]);
            pa[kk][3] = packh2(s[2 * kk + 1][2], s[2 * kk + 1][3]);
        }

        // ---- O = O*corr + P @ V  (V B-fragments via ldmatrix.trans) ----
#pragma unroll
        for (int ni = 0; ni < 8; ni++) {
            acc_o[ni][0] *= corr0; acc_o[ni][1] *= corr0;
            acc_o[ni][2] *= corr1; acc_o[ni][3] *= corr1;
        }
        uint32_t vbase = (uint32_t)__cvta_generic_to_shared(&Vh[buf][0]);
#pragma unroll
        for (int kk = 0; kk < 4; kk++) {
            int kc = kk * 16;
#pragma unroll
            for (int g = 0; g < 4; g++) {
                uint32_t r[4];
                uint32_t addr = vbase + (uint32_t)(((kc + lrow_off) * AST + g * 16 + lcol_off) * 2);
                ldsm_x4_trans(r, addr);
                uint32_t b0[2] = {r[0], r[1]};
                uint32_t b1[2] = {r[2], r[3]};
                mma_f16(acc_o[2 * g],     pa[kk], b0);
                mma_f16(acc_o[2 * g + 1], pa[kk], b1);
            }
        }
    }

    // epilogue: normalize, fp16, token-major [B,S,H,D]
    float inv0 = 1.0f / l_0;
    float inv1 = 1.0f / l_1;
    __half* ob = o + ((size_t)(b * S_ + qt * 64)) * E_ + h * 64;
#pragma unroll
    for (int ni = 0; ni < 8; ni++) {
        int cc = ni * 8 + 2 * c4;
        *reinterpret_cast<uint32_t*>(ob + (size_t)(m0 + r4) * E_ + cc) =
            packh2(acc_o[ni][0] * inv0, acc_o[ni][1] * inv0);
        *reinterpret_cast<uint32_t*>(ob + (size_t)(m0 + r4 + 8) * E_ + cc) =
            packh2(acc_o[ni][2] * inv1, acc_o[ni][3] * inv1);
    }
}

// ---------------- FP16 GEMM: 128 x BN_T x 32 tiles, 4-stage cp.async, templated BN ------
#define BM 128
#define BKH 32
#define HSTR 40
#define NSTG 4
#define A_STG (BM * HSTR)

template <int BN_T, int RELU, int RES, int HALFOUT>
__global__ __launch_bounds__(256) void hgemm_kernel(const __half* __restrict__ A,
                                                    const __half* __restrict__ Bt,
                                                    const float* __restrict__ bias,
                                                    const float* __restrict__ resid,
                                                    void* __restrict__ Cout,
                                                    int M, int N, int K)
{
    constexpr int B_STG  = BN_T * HSTR;
    constexpr int NFRAG  = BN_T / 32;       // n-fragments per warp (warp tile 64 x BN_T/4)
    constexpr int BLOADS = BN_T / 64;       // 16B chunks per thread for B tile

    extern __shared__ __half shh[];
    __half* Asm = shh;
    __half* Bsm = shh + NSTG * A_STG;

    const int tid  = threadIdx.x;
    const int lane = tid & 31;
    const int warp = tid >> 5;
    const int wm = warp >> 2;
    const int wn = warp & 3;
    const int m_w = wm * 64;
    const int n_w = wn * (BN_T / 4);
    const int r4 = lane >> 2;
    const int c4 = lane & 3;
    const int bx = blockIdx.x, by = blockIdx.y;

    const __half* Ab = A  + (size_t)by * BM * K;
    const __half* Bb = Bt + (size_t)bx * BN_T * K;

    auto load_tile = [&](int buf, int k0) {
        __half* Ad = Asm + buf * A_STG;
        __half* Bd = Bsm + buf * B_STG;
#pragma unroll
        for (int i = 0; i < 2; i++) {
            int idx = tid + i * 256;
            int row = idx >> 2, kq = (idx & 3) * 8;
            cp_async16(Ad + row * HSTR + kq, Ab + (size_t)row * K + k0 + kq);
        }
#pragma unroll
        for (int i = 0; i < BLOADS; i++) {
            int idx = tid + i * 256;
            int row = idx >> 2, kq = (idx & 3) * 8;
            cp_async16(Bd + row * HSTR + kq, Bb + (size_t)row * K + k0 + kq);
        }
        CP_COMMIT();
    };

    float acc[4][NFRAG][4] = {};

    const int nT = K / BKH;
    load_tile(0, 0);
    load_tile(1, BKH);
    load_tile(2, 2 * BKH);

#pragma unroll 1
    for (int t = 0; t < nT; t++) {
        int pend = nT - 1 - t;
        if (pend >= 2)      { CP_WAIT2(); }
        else if (pend == 1) { CP_WAIT1(); }
        else                { CP_WAIT0(); }
        __syncthreads();
        if (t + 3 < nT) load_tile((t + 3) % NSTG, (t + 3) * BKH);

        const __half* Ac = Asm + (t % NSTG) * A_STG;
        const __half* Bc = Bsm + (t % NSTG) * B_STG;
#pragma unroll
        for (int ks = 0; ks < 2; ks++) {
            const int kc = ks * 16;
            uint32_t a[4][4], b[NFRAG][2];
#pragma unroll
            for (int mi = 0; mi < 4; mi++) {
                int m0 = m_w + mi * 16;
                a[mi][0] = *reinterpret_cast<const uint32_t*>(Ac + (m0 + r4) * HSTR + kc + 2 * c4);
                a[mi][1] = *reinterpret_cast<const uint32_t*>(Ac + (m0 + r4 + 8) * HSTR + kc + 2 * c4);
                a[mi][2] = *reinterpret_cast<const uint32_t*>(Ac + (m0 + r4) * HSTR + kc + 2 * c4 + 8);
                a[mi][3] = *reinterpret_cast<const uint32_t*>(Ac + (m0 + r4 + 8) * HSTR + kc + 2 * c4 + 8);
            }
#pragma unroll
            for (int ni = 0; ni < NFRAG; ni++) {
                int n0 = n_w + ni * 8;
                b[ni][0] = *reinterpret_cast<const uint32_t*>(Bc + (n0 + r4) * HSTR + kc + 2 * c4);
                b[ni][1] = *reinterpret_cast<const uint32_t*>(Bc + (n0 + r4) * HSTR + kc + 2 * c4 + 8);
            }
#pragma unroll
            for (int mi = 0; mi < 4; mi++)
#pragma unroll
                for (int ni = 0; ni < NFRAG; ni++)
                    mma_f16(acc[mi][ni], a[mi], b[ni]);
        }
    }

    const int row_base = by * BM + m_w;
    const int col_base = bx * BN_T + n_w;
#pragma unroll
    for (int mi = 0; mi < 4; mi++) {
#pragma unroll
        for (int ni = 0; ni < NFRAG; ni++) {
            int c0 = col_base + ni * 8 + 2 * c4;
            float2 bb = *reinterpret_cast<const float2*>(bias + c0);
#pragma unroll
            for (int half = 0; half < 2; half++) {
                int r0 = row_base + mi * 16 + r4 + half * 8;
                float v0 = acc[mi][ni][half * 2]     + bb.x;
                float v1 = acc[mi][ni][half * 2 + 1] + bb.y;
                if (RELU) { v0 = fmaxf(v0, 0.f); v1 = fmaxf(v1, 0.f); }
                if (RES) {
                    float2 rr = *reinterpret_cast<const float2*>(resid + (size_t)r0 * N + c0);
                    v0 += rr.x; v1 += rr.y;
                }
                if (HALFOUT) {
                    *reinterpret_cast<__half2*>((__half*)Cout + (size_t)r0 * N + c0) =
                        __floats2half2_rn(v0, v1);
                } else {
                    float2 o2 = {v0, v1};
                    *reinterpret_cast<float2*>((float*)Cout + (size_t)r0 * N + c0) = o2;
                }
            }
        }
    }
}

#define GEMM_SMEM(BN_T) (NSTG * (A_STG + (BN_T) * HSTR) * 2)

// ---------------- launch ----------------
extern "C" void kernel_launch(void* const* d_in, const int* in_sizes, int n_in,
                              void* d_out, int out_size)
{
    (void)in_sizes; (void)n_in; (void)out_size;
    const float* x   = (const float*)d_in[0];
    const float* Wq  = (const float*)d_in[1];
    const float* Wk  = (const float*)d_in[2];
    const float* Wv  = (const float*)d_in[3];
    const float* Wo  = (const float*)d_in[4];
    const float* bo  = (const float*)d_in[5];
    const float* W1  = (const float*)d_in[6];
    const float* b1  = (const float*)d_in[7];
    const float* W2  = (const float*)d_in[8];
    const float* b2  = (const float*)d_in[9];
    const float* g1  = (const float*)d_in[10];
    const float* be1 = (const float*)d_in[11];
    const float* g2  = (const float*)d_in[12];
    const float* be2 = (const float*)d_in[13];
    float* out = (float*)d_out;

    float *x1;
    __half *nxh, *qb, *kb, *vb, *ob, *nx2, *h1, *woT, *w1T, *w2T, *wqT, *wkT, *wvT;
    cudaGetSymbolAddress((void**)&nxh, g_nxh);
    cudaGetSymbolAddress((void**)&qb,  g_q);
    cudaGetSymbolAddress((void**)&kb,  g_k);
    cudaGetSymbolAddress((void**)&vb,  g_v);
    cudaGetSymbolAddress((void**)&ob,  g_o);
    cudaGetSymbolAddress((void**)&x1,  g_x1);
    cudaGetSymbolAddress((void**)&nx2, g_nx2);
    cudaGetSymbolAddress((void**)&h1,  g_h1);
    cudaGetSymbolAddress((void**)&woT, g_woT);
    cudaGetSymbolAddress((void**)&w1T, g_w1T);
    cudaGetSymbolAddress((void**)&w2T, g_w2T);
    cudaGetSymbolAddress((void**)&wqT, g_wqT);
    cudaGetSymbolAddress((void**)&wkT, g_wkT);
    cudaGetSymbolAddress((void**)&wvT, g_wvT);

    cudaFuncSetAttribute((const void*)hgemm_kernel<64, 0, 1, 0>,
                         cudaFuncAttributeMaxDynamicSharedMemorySize, GEMM_SMEM(64));
    cudaFuncSetAttribute((const void*)hgemm_kernel<256, 1, 0, 1>,
                         cudaFuncAttributeMaxDynamicSharedMemorySize, GEMM_SMEM(256));

    // fork a side stream (capture-legal): big weight transposes run concurrently
    // with the LN1 -> QKV -> attention chain; join before the Wo GEMM.
    cudaStream_t s2 = 0;
    cudaEvent_t evFork = 0, evJoin = 0;
    bool forked = false;
    if (cudaStreamCreateWithFlags(&s2, cudaStreamNonBlocking) == cudaSuccess &&
        cudaEventCreateWithFlags(&evFork, cudaEventDisableTiming) == cudaSuccess &&
        cudaEventCreateWithFlags(&evJoin, cudaEventDisableTiming) == cudaSuccess) {
        forked = (cudaEventRecord(evFork, 0) == cudaSuccess) &&
                 (cudaStreamWaitEvent(s2, evFork, 0) == cudaSuccess);
    }
    cudaStream_t ts = forked ? s2 : 0;

    // 0a) big weight transposes (side stream if forked)
    transpose_h_kernel<<<dim3(E_ / 32, E_ / 32), dim3(32, 8), 0, ts>>>(Wo, woT, E_, E_);
    transpose_h_kernel<<<dim3(F_ / 32, E_ / 32), dim3(32, 8), 0, ts>>>(W1, w1T, E_, F_);
    transpose_h_kernel<<<dim3(E_ / 32, F_ / 32), dim3(32, 8), 0, ts>>>(W2, w2T, F_, E_);
    if (forked) {
        cudaEventRecord(evJoin, s2);
    }

    // 0b) tiny per-head weight transposes (main stream; QKV depends on them)
    transpose_h_kernel<<<dim3(2, 2), dim3(32, 8)>>>(Wq, wqT, D_, D_);
    transpose_h_kernel<<<dim3(2, 2), dim3(32, 8)>>>(Wk, wkT, D_, D_);
    transpose_h_kernel<<<dim3(2, 2), dim3(32, 8)>>>(Wv, wvT, D_, D_);
    // 1) LN1 (fp16 out)
    ln_kernel<1><<<TOK, 256>>>(x, g1, be1, nxh);
    // 2) QKV projections (fp16 mma)
    qkv_kernel<<<dim3(S_ / 64, H_, B_), 128>>>(nxh, wqT, wkT, wvT, qb, kb, vb);
    // 3) causal flash attention -> o fp16
    attn_kernel<<<dim3(S_ / 64, H_, B_), 128>>>(qb, kb, vb, ob);

    // join: Wo/W1/W2 transposes must be done before the GEMMs
    if (forked) {
        cudaStreamWaitEvent(0, evJoin, 0);
    }

    // 4) x1 = x + o @ Wo + bo   (f32 out; BN=64 -> 1024 blocks, ~99% wave eff)
    hgemm_kernel<64, 0, 1, 0><<<dim3(E_ / 64, TOK / BM), 256, GEMM_SMEM(64)>>>(ob, woT, bo, x, x1, TOK, E_, E_);
    // 5) LN2 (fp16 out)
    ln_kernel<1><<<TOK, 256>>>(x1, g2, be2, nx2);
    // 6) h1 = relu(nx2 @ W1 + b1)  (fp16 out; BN=256 -> 1024 blocks already)
    hgemm_kernel<256, 1, 0, 1><<<dim3(F_ / 256, TOK / BM), 256, GEMM_SMEM(256)>>>(nx2, w1T, b1, nullptr, h1, TOK, F_, E_);
    // 7) out = x1 + h1 @ W2 + b2   (f32 out; BN=64 -> 1024 blocks)
    hgemm_kernel<64, 0, 1, 0><<<dim3(E_ / 64, TOK / BM), 256, GEMM_SMEM(64)>>>(h1, w2T, b2, x1, out, TOK, E_, F_);
    // note: s2/evFork/evJoin intentionally not destroyed — handles are tiny,
    // kernel_launch is called only a few times, and destroying mid-capture is risky.
}

// round 16
// speedup vs baseline: 1.0346x; 1.0346x over previous
#include <cuda_runtime.h>
#include <cuda_fp16.h>
#include <math.h>
#include <stdint.h>

#define B_ 8
#define S_ 1024
#define E_ 1024
#define H_ 16
#define D_ 64
#define F_ 4096
#define TOK (B_ * S_)  // 8192

// ---------------- scratch (static device globals; no allocation) ----------------
__device__ __half g_nxh[(size_t)TOK * E_];
__device__ __half g_q  [(size_t)TOK * E_];
__device__ __half g_k  [(size_t)TOK * E_];
__device__ __half g_v  [(size_t)TOK * E_];
__device__ __half g_o  [(size_t)TOK * E_];
__device__ float  g_x1 [(size_t)TOK * E_];
__device__ __half g_nx2[(size_t)TOK * E_];
__device__ __half g_h1 [(size_t)TOK * F_];
__device__ __half g_woT[(size_t)E_ * E_];
__device__ __half g_w1T[(size_t)F_ * E_];
__device__ __half g_w2T[(size_t)E_ * F_];

// ---------------- helpers ----------------
__device__ __forceinline__ void cp_async16(void* smem, const void* gmem) {
    uint32_t s = (uint32_t)__cvta_generic_to_shared(smem);
    asm volatile("cp.async.cg.shared.global [%0], [%1], 16;\n" :: "r"(s), "l"(gmem));
}
#define CP_COMMIT() asm volatile("cp.async.commit_group;\n" ::: "memory")
#define CP_WAIT0()  asm volatile("cp.async.wait_group 0;\n" ::: "memory")
#define CP_WAIT1()  asm volatile("cp.async.wait_group 1;\n" ::: "memory")
#define CP_WAIT2()  asm volatile("cp.async.wait_group 2;\n" ::: "memory")

__device__ __forceinline__ void mma_f16(float c[4], const uint32_t a[4], const uint32_t b[2]) {
    asm volatile(
        "mma.sync.aligned.m16n8k16.row.col.f32.f16.f16.f32 "
        "{%0,%1,%2,%3}, {%4,%5,%6,%7}, {%8,%9}, {%0,%1,%2,%3};\n"
        : "+f"(c[0]), "+f"(c[1]), "+f"(c[2]), "+f"(c[3])
        : "r"(a[0]), "r"(a[1]), "r"(a[2]), "r"(a[3]), "r"(b[0]), "r"(b[1]));
}
__device__ __forceinline__ uint32_t packh2(float a, float b) {
    __half2 h = __floats2half2_rn(a, b);
    return *reinterpret_cast<uint32_t*>(&h);
}
__device__ __forceinline__ void ldsm_x4_trans(uint32_t r[4], uint32_t saddr) {
    asm volatile("ldmatrix.sync.aligned.m8n8.x4.trans.shared.b16 {%0,%1,%2,%3}, [%4];"
                 : "=r"(r[0]), "=r"(r[1]), "=r"(r[2]), "=r"(r[3]) : "r"(saddr));
}

// ---------------- weight transpose + fp16 round: in [K][N] f32 -> out [N][K] f16 ----------
__global__ __launch_bounds__(256) void transpose_h_kernel(const float* __restrict__ in,
                                                          __half* __restrict__ out,
                                                          int K, int N)
{
    __shared__ float tile[32][33];
    int bx = blockIdx.x;
    int by = blockIdx.y;
    int x = bx * 32 + threadIdx.x;
    int y0 = by * 32 + threadIdx.y;
#pragma unroll
    for (int j = 0; j < 32; j += 8)
        tile[threadIdx.y + j][threadIdx.x] = in[(size_t)(y0 + j) * N + x];
    __syncthreads();
    int xo = by * 32 + threadIdx.x;
    int yo = bx * 32 + threadIdx.y;
#pragma unroll
    for (int j = 0; j < 32; j += 8)
        out[(size_t)(yo + j) * K + xo] = __float2half_rn(tile[threadIdx.x][threadIdx.y + j]);
}

// ---------------- LayerNorm: one block per row of 1024 ----------------
template <int HALFOUT>
__global__ __launch_bounds__(256) void ln_kernel(const float* __restrict__ x,
                                                 const float* __restrict__ g,
                                                 const float* __restrict__ be,
                                                 void* __restrict__ out)
{
    int row = blockIdx.x;
    int tid = threadIdx.x;
    const float4* xr = reinterpret_cast<const float4*>(x + (size_t)row * E_);
    float4 a = xr[tid];
    float s  = a.x + a.y + a.z + a.w;
    float ss = a.x * a.x + a.y * a.y + a.z * a.z + a.w * a.w;
#pragma unroll
    for (int o = 16; o > 0; o >>= 1) {
        s  += __shfl_xor_sync(0xffffffffu, s,  o);
        ss += __shfl_xor_sync(0xffffffffu, ss, o);
    }
    __shared__ float sm[8], sm2[8];
    int w = tid >> 5, lane = tid & 31;
    if (lane == 0) { sm[w] = s; sm2[w] = ss; }
    __syncthreads();
    if (tid < 32) {
        s  = (tid < 8) ? sm[tid]  : 0.f;
        ss = (tid < 8) ? sm2[tid] : 0.f;
#pragma unroll
        for (int o = 4; o > 0; o >>= 1) {
            s  += __shfl_xor_sync(0xffffffffu, s,  o);
            ss += __shfl_xor_sync(0xffffffffu, ss, o);
        }
        if (tid == 0) { sm[0] = s; sm2[0] = ss; }
    }
    __syncthreads();
    float mean = sm[0] * (1.0f / E_);
    float var  = sm2[0] * (1.0f / E_) - mean * mean;
    float inv  = rsqrtf(var + 1e-5f);
    float4 gg = reinterpret_cast<const float4*>(g)[tid];
    float4 bb = reinterpret_cast<const float4*>(be)[tid];
    float4 o4;
    o4.x = (a.x - mean) * inv * gg.x + bb.x;
    o4.y = (a.y - mean) * inv * gg.y + bb.y;
    o4.z = (a.z - mean) * inv * gg.z + bb.z;
    o4.w = (a.w - mean) * inv * gg.w + bb.w;
    if (HALFOUT) {
        __half2* op = reinterpret_cast<__half2*>((__half*)out + (size_t)row * E_ + tid * 4);
        op[0] = __floats2half2_rn(o4.x, o4.y);
        op[1] = __floats2half2_rn(o4.z, o4.w);
    } else {
        reinterpret_cast<float4*>((float*)out + (size_t)row * E_)[tid] = o4;
    }
}

// ---------------- QKV projections via fp16 mma, raw f32 weights (ldmatrix.trans B) -----
#define AST 72   // halves; conflict-free for fragment pattern

__global__ __launch_bounds__(128) void qkv_kernel(const __half* __restrict__ nxh,
                                                  const float* __restrict__ Wq,
                                                  const float* __restrict__ Wk,
                                                  const float* __restrict__ Wv,
                                                  __half* __restrict__ q,
                                                  __half* __restrict__ k,
                                                  __half* __restrict__ v)
{
    __shared__ __half Xh[64 * AST];
    __shared__ __half Wh[64 * AST];    // W row-major [k][n], fp16
    int st = blockIdx.x, h = blockIdx.y, b = blockIdx.z;
    int tid  = threadIdx.x;
    int lane = tid & 31, warp = tid >> 5;
    int m0 = warp * 16;
    int r4 = lane >> 2, c4 = lane & 3;

    // ldmatrix.trans per-lane address offsets (B operand from row-major [k][n])
    const int lm = lane >> 3;
    const int lj = lane & 7;
    const int lrow_off = (lm & 1) * 8 + lj;
    const int lcol_off = (lm >> 1) * 8;

#pragma unroll
    for (int it = 0; it < 4; it++) {
        int idx = tid + it * 128;
        int r = idx >> 3, c8 = (idx & 7) * 8;
        uint4 raw = *reinterpret_cast<const uint4*>(
            nxh + ((size_t)(b * S_ + st * 64 + r)) * E_ + h * 64 + c8);
        *reinterpret_cast<uint4*>(Xh + r * AST + c8) = raw;
    }

    const float* Wm[3] = {Wq, Wk, Wv};
    __half*      Om[3] = {q, k, v};
    size_t obase = ((size_t)(b * H_ + h) * S_ + st * 64) * D_;
    uint32_t wbase = (uint32_t)__cvta_generic_to_shared(Wh);

#pragma unroll 1
    for (int m = 0; m < 3; m++) {
        __syncthreads();
        // stage W [64][64] f32 -> fp16 row-major (no transpose)
#pragma unroll
        for (int it = 0; it < 8; it++) {
            int idx = tid + it * 128;               // 1024 float4 chunks
            int r = idx >> 4, cc = (idx & 15) * 4;
            float4 wv4 = *reinterpret_cast<const float4*>(Wm[m] + (size_t)r * 64 + cc);
            uint32_t* wp = reinterpret_cast<uint32_t*>(Wh + r * AST + cc);
            wp[0] = packh2(wv4.x, wv4.y);
            wp[1] = packh2(wv4.z, wv4.w);
        }
        __syncthreads();

        float acc[8][4] = {};
#pragma unroll
        for (int ks = 0; ks < 4; ks++) {
            int kc = ks * 16;
            uint32_t a[4];
            a[0] = *reinterpret_cast<const uint32_t*>(Xh + (m0 + r4) * AST + kc + 2 * c4);
            a[1] = *reinterpret_cast<const uint32_t*>(Xh + (m0 + r4 + 8) * AST + kc + 2 * c4);
            a[2] = *reinterpret_cast<const uint32_t*>(Xh + (m0 + r4) * AST + kc + 2 * c4 + 8);
            a[3] = *reinterpret_cast<const uint32_t*>(Xh + (m0 + r4 + 8) * AST + kc + 2 * c4 + 8);
#pragma unroll
            for (int g = 0; g < 4; g++) {
                uint32_t r[4];
                uint32_t addr = wbase + (uint32_t)(((kc + lrow_off) * AST + g * 16 + lcol_off) * 2);
                ldsm_x4_trans(r, addr);
                uint32_t b0[2] = {r[0], r[1]};
                uint32_t b1[2] = {r[2], r[3]};
                mma_f16(acc[2 * g],     a, b0);
                mma_f16(acc[2 * g + 1], a, b1);
            }
        }
        __half* dst = Om[m] + obase;
#pragma unroll
        for (int ni = 0; ni < 8; ni++) {
            int cc = ni * 8 + 2 * c4;
            *reinterpret_cast<uint32_t*>(dst + (m0 + r4) * D_ + cc)     = packh2(acc[ni][0], acc[ni][1]);
            *reinterpret_cast<uint32_t*>(dst + (m0 + r4 + 8) * D_ + cc) = packh2(acc[ni][2], acc[ni][3]);
        }
    }
}

// ---------------- Causal flash attention: register softmax, ldmatrix.trans V,
//                  cp.async double-buffered K/V, heaviest-first scheduling ------------
__global__ __launch_bounds__(128) void attn_kernel(const __half* __restrict__ q,
                                                   const __half* __restrict__ k,
                                                   const __half* __restrict__ v,
                                                   __half* __restrict__ o)
{
    __shared__ __half Qh[64 * AST];
    __shared__ __half Kh[2][64 * AST];
    __shared__ __half Vh[2][64 * AST];   // row-major [s][d]

    // heaviest-first: high qt blocks launch first
    int qt = (int)gridDim.x - 1 - (int)blockIdx.x;
    int h = blockIdx.y, b = blockIdx.z;
    int tid  = threadIdx.x;
    int lane = tid & 31, warp = tid >> 5;
    int m0 = warp * 16;
    int r4 = lane >> 2, c4 = lane & 3;
    size_t head_base = (size_t)(b * H_ + h) * S_ * D_;
    const __half2 hscale = __float2half2_rn(0.03125f);  // 1/32 exact

    // ldmatrix.trans per-lane address offsets (within a V tile)
    const int lm = lane >> 3;
    const int lj = lane & 7;
    const int lrow_off = (lm & 1) * 8 + lj;
    const int lcol_off = (lm >> 1) * 8;

    // load Q (scaled)
#pragma unroll
    for (int it = 0; it < 4; it++) {
        int idx = tid + it * 128;
        int r = idx >> 3, c8 = (idx & 7) * 8;
        uint4 raw = *reinterpret_cast<const uint4*>(q + head_base + (size_t)(qt * 64 + r) * 64 + c8);
        __half2* hp = reinterpret_cast<__half2*>(&raw);
#pragma unroll
        for (int j = 0; j < 4; j++) hp[j] = __hmul2(hp[j], hscale);
        *reinterpret_cast<uint4*>(Qh + r * AST + c8) = raw;
    }

    auto stage = [&](int buf, int kt) {
#pragma unroll
        for (int it = 0; it < 4; it++) {
            int idx = tid + it * 128;
            int r = idx >> 3, c8 = (idx & 7) * 8;
            cp_async16(&Kh[buf][r * AST + c8], k + head_base + (size_t)(kt * 64 + r) * 64 + c8);
            cp_async16(&Vh[buf][r * AST + c8], v + head_base + (size_t)(kt * 64 + r) * 64 + c8);
        }
        CP_COMMIT();
    };

    float m_0 = -1e30f, m_1 = -1e30f, l_0 = 0.f, l_1 = 0.f;
    float acc_o[8][4] = {};

    stage(0, 0);

    for (int kt = 0; kt <= qt; kt++) {
        int buf = kt & 1;
        CP_WAIT0();
        __syncthreads();
        if (kt + 1 <= qt) stage(buf ^ 1, kt + 1);

        // ---- S = Q @ K^T : warp computes 16x64 in registers ----
        float s[8][4] = {};
#pragma unroll
        for (int ks = 0; ks < 4; ks++) {
            int kc = ks * 16;
            uint32_t a[4];
            a[0] = *reinterpret_cast<const uint32_t*>(Qh + (m0 + r4) * AST + kc + 2 * c4);
            a[1] = *reinterpret_cast<const uint32_t*>(Qh + (m0 + r4 + 8) * AST + kc + 2 * c4);
            a[2] = *reinterpret_cast<const uint32_t*>(Qh + (m0 + r4) * AST + kc + 2 * c4 + 8);
            a[3] = *reinterpret_cast<const uint32_t*>(Qh + (m0 + r4 + 8) * AST + kc + 2 * c4 + 8);
#pragma unroll
            for (int ni = 0; ni < 8; ni++) {
                int n0 = ni * 8;
                uint32_t bf[2];
                bf[0] = *reinterpret_cast<const uint32_t*>(&Kh[buf][(n0 + r4) * AST + kc + 2 * c4]);
                bf[1] = *reinterpret_cast<const uint32_t*>(&Kh[buf][(n0 + r4) * AST + kc + 2 * c4 + 8]);
                mma_f16(s[ni], a, bf);
            }
        }

        if (kt == qt) {
            int row0 = m0 + r4, row1 = m0 + r4 + 8;
#pragma unroll
            for (int ni = 0; ni < 8; ni++) {
                int col = ni * 8 + 2 * c4;
                if (col > row0)     s[ni][0] = -1e30f;
                if (col + 1 > row0) s[ni][1] = -1e30f;
                if (col > row1)     s[ni][2] = -1e30f;
                if (col + 1 > row1) s[ni][3] = -1e30f;
            }
        }

        // ---- register softmax ----
        float mx0 = -1e30f, mx1 = -1e30f;
#pragma unroll
        for (int ni = 0; ni < 8; ni++) {
            mx0 = fmaxf(mx0, fmaxf(s[ni][0], s[ni][1]));
            mx1 = fmaxf(mx1, fmaxf(s[ni][2], s[ni][3]));
        }
        mx0 = fmaxf(mx0, __shfl_xor_sync(0xffffffffu, mx0, 1));
        mx0 = fmaxf(mx0, __shfl_xor_sync(0xffffffffu, mx0, 2));
        mx1 = fmaxf(mx1, __shfl_xor_sync(0xffffffffu, mx1, 1));
        mx1 = fmaxf(mx1, __shfl_xor_sync(0xffffffffu, mx1, 2));

        float mn0 = fmaxf(m_0, mx0), mn1 = fmaxf(m_1, mx1);
        float corr0 = expf(m_0 - mn0), corr1 = expf(m_1 - mn1);
        float rs0 = 0.f, rs1 = 0.f;
#pragma unroll
        for (int ni = 0; ni < 8; ni++) {
            s[ni][0] = expf(s[ni][0] - mn0);
            s[ni][1] = expf(s[ni][1] - mn0);
            s[ni][2] = expf(s[ni][2] - mn1);
            s[ni][3] = expf(s[ni][3] - mn1);
            rs0 += s[ni][0] + s[ni][1];
            rs1 += s[ni][2] + s[ni][3];
        }
        rs0 += __shfl_xor_sync(0xffffffffu, rs0, 1);
        rs0 += __shfl_xor_sync(0xffffffffu, rs0, 2);
        rs1 += __shfl_xor_sync(0xffffffffu, rs1, 1);
        rs1 += __shfl_xor_sync(0xffffffffu, rs1, 2);
        l_0 = l_0 * corr0 + rs0;  m_0 = mn0;
        l_1 = l_1 * corr1 + rs1;  m_1 = mn1;

        // pack P into A-fragments (S C-frag layout == P A-frag layout)
        uint32_t pa[4][4];
#pragma unroll
        for (int kk = 0; kk < 4; kk++) {
            pa[kk][0] = packh2(s[2 * kk][0],     s[2 * kk][1]);
            pa[kk][1] = packh2(s[2 * kk][2],     s[2 * kk][3]);
            pa[kk][2] = packh2(s[2 * kk + 1][0], s[2 * kk + 1][1]);
            pa[kk][3] = packh2(s[2 * kk + 1][2], s[2 * kk + 1][3]);
        }

        // ---- O = O*corr + P @ V  (V B-fragments via ldmatrix.trans) ----
#pragma unroll
        for (int ni = 0; ni < 8; ni++) {
            acc_o[ni][0] *= corr0; acc_o[ni][1] *= corr0;
            acc_o[ni][2] *= corr1; acc_o[ni][3] *= corr1;
        }
        uint32_t vbase = (uint32_t)__cvta_generic_to_shared(&Vh[buf][0]);
#pragma unroll
        for (int kk = 0; kk < 4; kk++) {
            int kc = kk * 16;
#pragma unroll
            for (int g = 0; g < 4; g++) {
                uint32_t r[4];
                uint32_t addr = vbase + (uint32_t)(((kc + lrow_off) * AST + g * 16 + lcol_off) * 2);
                ldsm_x4_trans(r, addr);
                uint32_t b0[2] = {r[0], r[1]};
                uint32_t b1[2] = {r[2], r[3]};
                mma_f16(acc_o[2 * g],     pa[kk], b0);
                mma_f16(acc_o[2 * g + 1], pa[kk], b1);
            }
        }
    }

    // epilogue: normalize, fp16, token-major [B,S,H,D]
    float inv0 = 1.0f / l_0;
    float inv1 = 1.0f / l_1;
    __half* ob = o + ((size_t)(b * S_ + qt * 64)) * E_ + h * 64;
#pragma unroll
    for (int ni = 0; ni < 8; ni++) {
        int cc = ni * 8 + 2 * c4;
        *reinterpret_cast<uint32_t*>(ob + (size_t)(m0 + r4) * E_ + cc) =
            packh2(acc_o[ni][0] * inv0, acc_o[ni][1] * inv0);
        *reinterpret_cast<uint32_t*>(ob + (size_t)(m0 + r4 + 8) * E_ + cc) =
            packh2(acc_o[ni][2] * inv1, acc_o[ni][3] * inv1);
    }
}

// ---------------- FP16 GEMM: 128x256x32 tiles, warp 64x64, 4-stage cp.async ------------
#define BM 128
#define BN 256
#define BKH 32
#define HSTR 40
#define NSTG 4
#define A_STG (BM * HSTR)
#define B_STG (BN * HSTR)
#define GEMM_SMEM_BYTES (NSTG * (A_STG + B_STG) * 2)   // 122880

template <int RELU, int RES, int HALFOUT>
__global__ __launch_bounds__(256) void hgemm_kernel(const __half* __restrict__ A,
                                                    const __half* __restrict__ Bt,
                                                    const float* __restrict__ bias,
                                                    const float* __restrict__ resid,
                                                    void* __restrict__ Cout,
                                                    int M, int N, int K)
{
    extern __shared__ __half shh[];
    __half* Asm = shh;
    __half* Bsm = shh + NSTG * A_STG;

    const int tid  = threadIdx.x;
    const int lane = tid & 31;
    const int warp = tid >> 5;
    const int wm = warp >> 2;
    const int wn = warp & 3;
    const int m_w = wm * 64;
    const int n_w = wn * 64;
    const int r4 = lane >> 2;
    const int c4 = lane & 3;
    const int bx = blockIdx.x, by = blockIdx.y;

    const __half* Ab = A  + (size_t)by * BM * K;
    const __half* Bb = Bt + (size_t)bx * BN * K;

    auto load_tile = [&](int buf, int k0) {
        __half* Ad = Asm + buf * A_STG;
        __half* Bd = Bsm + buf * B_STG;
#pragma unroll
        for (int i = 0; i < 2; i++) {
            int idx = tid + i * 256;
            int row = idx >> 2, kq = (idx & 3) * 8;
            cp_async16(Ad + row * HSTR + kq, Ab + (size_t)row * K + k0 + kq);
        }
#pragma unroll
        for (int i = 0; i < 4; i++) {
            int idx = tid + i * 256;
            int row = idx >> 2, kq = (idx & 3) * 8;
            cp_async16(Bd + row * HSTR + kq, Bb + (size_t)row * K + k0 + kq);
        }
        CP_COMMIT();
    };

    float acc[4][8][4] = {};

    const int nT = K / BKH;
    load_tile(0, 0);
    load_tile(1, BKH);
    load_tile(2, 2 * BKH);

#pragma unroll 1
    for (int t = 0; t < nT; t++) {
        int pend = nT - 1 - t;
        if (pend >= 2)      { CP_WAIT2(); }
        else if (pend == 1) { CP_WAIT1(); }
        else                { CP_WAIT0(); }
        __syncthreads();
        if (t + 3 < nT) load_tile((t + 3) % NSTG, (t + 3) * BKH);

        const __half* Ac = Asm + (t % NSTG) * A_STG;
        const __half* Bc = Bsm + (t % NSTG) * B_STG;
#pragma unroll
        for (int ks = 0; ks < 2; ks++) {
            const int kc = ks * 16;
            uint32_t a[4][4], b[8][2];
#pragma unroll
            for (int mi = 0; mi < 4; mi++) {
                int m0 = m_w + mi * 16;
                a[mi][0] = *reinterpret_cast<const uint32_t*>(Ac + (m0 + r4) * HSTR + kc + 2 * c4);
                a[mi][1] = *reinterpret_cast<const uint32_t*>(Ac + (m0 + r4 + 8) * HSTR + kc + 2 * c4);
                a[mi][2] = *reinterpret_cast<const uint32_t*>(Ac + (m0 + r4) * HSTR + kc + 2 * c4 + 8);
                a[mi][3] = *reinterpret_cast<const uint32_t*>(Ac + (m0 + r4 + 8) * HSTR + kc + 2 * c4 + 8);
            }
#pragma unroll
            for (int ni = 0; ni < 8; ni++) {
                int n0 = n_w + ni * 8;
                b[ni][0] = *reinterpret_cast<const uint32_t*>(Bc + (n0 + r4) * HSTR + kc + 2 * c4);
                b[ni][1] = *reinterpret_cast<const uint32_t*>(Bc + (n0 + r4) * HSTR + kc + 2 * c4 + 8);
            }
#pragma unroll
            for (int mi = 0; mi < 4; mi++)
#pragma unroll
                for (int ni = 0; ni < 8; ni++)
                    mma_f16(acc[mi][ni], a[mi], b[ni]);
        }
    }

    const int row_base = by * BM + m_w;
    const int col_base = bx * BN + n_w;
#pragma unroll
    for (int mi = 0; mi < 4; mi++) {
#pragma unroll
        for (int ni = 0; ni < 8; ni++) {
            int c0 = col_base + ni * 8 + 2 * c4;
            float2 bb = *reinterpret_cast<const float2*>(bias + c0);
#pragma unroll
            for (int half = 0; half < 2; half++) {
                int r0 = row_base + mi * 16 + r4 + half * 8;
                float v0 = acc[mi][ni][half * 2]     + bb.x;
                float v1 = acc[mi][ni][half * 2 + 1] + bb.y;
                if (RELU) { v0 = fmaxf(v0, 0.f); v1 = fmaxf(v1, 0.f); }
                if (RES) {
                    float2 rr = *reinterpret_cast<const float2*>(resid + (size_t)r0 * N + c0);
                    v0 += rr.x; v1 += rr.y;
                }
                if (HALFOUT) {
                    *reinterpret_cast<__half2*>((__half*)Cout + (size_t)r0 * N + c0) =
                        __floats2half2_rn(v0, v1);
                } else {
                    float2 o2 = {v0, v1};
                    *reinterpret_cast<float2*>((float*)Cout + (size_t)r0 * N + c0) = o2;
                }
            }
        }
    }
}

// ---------------- launch ----------------
extern "C" void kernel_launch(void* const* d_in, const int* in_sizes, int n_in,
                              void* d_out, int out_size)
{
    (void)in_sizes; (void)n_in; (void)out_size;
    const float* x   = (const float*)d_in[0];
    const float* Wq  = (const float*)d_in[1];
    const float* Wk  = (const float*)d_in[2];
    const float* Wv  = (const float*)d_in[3];
    const float* Wo  = (const float*)d_in[4];
    const float* bo  = (const float*)d_in[5];
    const float* W1  = (const float*)d_in[6];
    const float* b1  = (const float*)d_in[7];
    const float* W2  = (const float*)d_in[8];
    const float* b2  = (const float*)d_in[9];
    const float* g1  = (const float*)d_in[10];
    const float* be1 = (const float*)d_in[11];
    const float* g2  = (const float*)d_in[12];
    const float* be2 = (const float*)d_in[13];
    float* out = (float*)d_out;

    float *x1;
    __half *nxh, *qb, *kb, *vb, *ob, *nx2, *h1, *woT, *w1T, *w2T;
    cudaGetSymbolAddress((void**)&nxh, g_nxh);
    cudaGetSymbolAddress((void**)&qb,  g_q);
    cudaGetSymbolAddress((void**)&kb,  g_k);
    cudaGetSymbolAddress((void**)&vb,  g_v);
    cudaGetSymbolAddress((void**)&ob,  g_o);
    cudaGetSymbolAddress((void**)&x1,  g_x1);
    cudaGetSymbolAddress((void**)&nx2, g_nx2);
    cudaGetSymbolAddress((void**)&h1,  g_h1);
    cudaGetSymbolAddress((void**)&woT, g_woT);
    cudaGetSymbolAddress((void**)&w1T, g_w1T);
    cudaGetSymbolAddress((void**)&w2T, g_w2T);

    cudaFuncSetAttribute(hgemm_kernel<0, 1, 0>, cudaFuncAttributeMaxDynamicSharedMemorySize,
                         GEMM_SMEM_BYTES);
    cudaFuncSetAttribute(hgemm_kernel<1, 0, 1>, cudaFuncAttributeMaxDynamicSharedMemorySize,
                         GEMM_SMEM_BYTES);

    // fork a side stream (capture-legal): big weight transposes run concurrently
    // with the LN1 -> QKV -> attention chain; join before the Wo GEMM.
    cudaStream_t s2 = 0;
    cudaEvent_t evFork = 0, evJoin = 0;
    bool forked = false;
    if (cudaStreamCreateWithFlags(&s2, cudaStreamNonBlocking) == cudaSuccess &&
        cudaEventCreateWithFlags(&evFork, cudaEventDisableTiming) == cudaSuccess &&
        cudaEventCreateWithFlags(&evJoin, cudaEventDisableTiming) == cudaSuccess) {
        forked = (cudaEventRecord(evFork, 0) == cudaSuccess) &&
                 (cudaStreamWaitEvent(s2, evFork, 0) == cudaSuccess);
    }
    cudaStream_t ts = forked ? s2 : 0;

    // 0) big weight transposes (side stream if forked)
    transpose_h_kernel<<<dim3(E_ / 32, E_ / 32), dim3(32, 8), 0, ts>>>(Wo, woT, E_, E_);
    transpose_h_kernel<<<dim3(F_ / 32, E_ / 32), dim3(32, 8), 0, ts>>>(W1, w1T, E_, F_);
    transpose_h_kernel<<<dim3(E_ / 32, F_ / 32), dim3(32, 8), 0, ts>>>(W2, w2T, F_, E_);
    if (forked) {
        cudaEventRecord(evJoin, s2);
    }

    // 1) LN1 (fp16 out)
    ln_kernel<1><<<TOK, 256>>>(x, g1, be1, nxh);
    // 2) QKV projections (fp16 mma, raw f32 weights staged in-kernel)
    qkv_kernel<<<dim3(S_ / 64, H_, B_), 128>>>(nxh, Wq, Wk, Wv, qb, kb, vb);
    // 3) causal flash attention -> o fp16
    attn_kernel<<<dim3(S_ / 64, H_, B_), 128>>>(qb, kb, vb, ob);

    // join: Wo/W1/W2 transposes must be done before the GEMMs
    if (forked) {
        cudaStreamWaitEvent(0, evJoin, 0);
    }

    // 4) x1 = x + o @ Wo + bo   (f32 out)
    hgemm_kernel<0, 1, 0><<<dim3(E_ / BN, TOK / BM), 256, GEMM_SMEM_BYTES>>>(ob, woT, bo, x, x1, TOK, E_, E_);
    // 5) LN2 (fp16 out)
    ln_kernel<1><<<TOK, 256>>>(x1, g2, be2, nx2);
    // 6) h1 = relu(nx2 @ W1 + b1)  (fp16 out)
    hgemm_kernel<1, 0, 1><<<dim3(F_ / BN, TOK / BM), 256, GEMM_SMEM_BYTES>>>(nx2, w1T, b1, nullptr, h1, TOK, F_, E_);
    // 7) out = x1 + h1 @ W2 + b2   (f32 out)
    hgemm_kernel<0, 1, 0><<<dim3(E_ / BN, TOK / BM), 256, GEMM_SMEM_BYTES>>>(h1, w2T, b2, x1, out, TOK, E_, F_);
    // note: s2/evFork/evJoin intentionally not destroyed — handles are tiny,
    // kernel_launch is called only a few times, and destroying mid-capture is risky.
}

// round 17
// speedup vs baseline: 1.0454x; 1.0104x over previous
#include <cuda_runtime.h>
#include <cuda_fp16.h>
#include <math.h>
#include <stdint.h>

#define B_ 8
#define S_ 1024
#define E_ 1024
#define H_ 16
#define D_ 64
#define F_ 4096
#define TOK (B_ * S_)  // 8192

// ---------------- scratch (static device globals; no allocation) ----------------
__device__ __half g_nxh[(size_t)TOK * E_];
__device__ __half g_q  [(size_t)TOK * E_];
__device__ __half g_k  [(size_t)TOK * E_];
__device__ __half g_v  [(size_t)TOK * E_];
__device__ __half g_o  [(size_t)TOK * E_];
__device__ float  g_x1 [(size_t)TOK * E_];
__device__ __half g_nx2[(size_t)TOK * E_];
__device__ __half g_h1 [(size_t)TOK * F_];
__device__ __half g_woT[(size_t)E_ * E_];
__device__ __half g_w1T[(size_t)F_ * E_];
__device__ __half g_w2T[(size_t)E_ * F_];

// ---------------- helpers ----------------
__device__ __forceinline__ void cp_async16(void* smem, const void* gmem) {
    uint32_t s = (uint32_t)__cvta_generic_to_shared(smem);
    asm volatile("cp.async.cg.shared.global [%0], [%1], 16;\n" :: "r"(s), "l"(gmem));
}
#define CP_COMMIT() asm volatile("cp.async.commit_group;\n" ::: "memory")
#define CP_WAIT0()  asm volatile("cp.async.wait_group 0;\n" ::: "memory")
#define CP_WAIT1()  asm volatile("cp.async.wait_group 1;\n" ::: "memory")
#define CP_WAIT2()  asm volatile("cp.async.wait_group 2;\n" ::: "memory")

__device__ __forceinline__ void mma_f16(float c[4], const uint32_t a[4], const uint32_t b[2]) {
    asm volatile(
        "mma.sync.aligned.m16n8k16.row.col.f32.f16.f16.f32 "
        "{%0,%1,%2,%3}, {%4,%5,%6,%7}, {%8,%9}, {%0,%1,%2,%3};\n"
        : "+f"(c[0]), "+f"(c[1]), "+f"(c[2]), "+f"(c[3])
        : "r"(a[0]), "r"(a[1]), "r"(a[2]), "r"(a[3]), "r"(b[0]), "r"(b[1]));
}
__device__ __forceinline__ uint32_t packh2(float a, float b) {
    __half2 h = __floats2half2_rn(a, b);
    return *reinterpret_cast<uint32_t*>(&h);
}
__device__ __forceinline__ void ldsm_x4_trans(uint32_t r[4], uint32_t saddr) {
    asm volatile("ldmatrix.sync.aligned.m8n8.x4.trans.shared.b16 {%0,%1,%2,%3}, [%4];"
                 : "=r"(r[0]), "=r"(r[1]), "=r"(r[2]), "=r"(r[3]) : "r"(saddr));
}

// ---------------- weight transpose + fp16 round: in [K][N] f32 -> out [N][K] f16 ----------
__global__ __launch_bounds__(256) void transpose_h_kernel(const float* __restrict__ in,
                                                          __half* __restrict__ out,
                                                          int K, int N)
{
    __shared__ float tile[32][33];
    int bx = blockIdx.x;
    int by = blockIdx.y;
    int x = bx * 32 + threadIdx.x;
    int y0 = by * 32 + threadIdx.y;
#pragma unroll
    for (int j = 0; j < 32; j += 8)
        tile[threadIdx.y + j][threadIdx.x] = in[(size_t)(y0 + j) * N + x];
    __syncthreads();
    int xo = by * 32 + threadIdx.x;
    int yo = bx * 32 + threadIdx.y;
#pragma unroll
    for (int j = 0; j < 32; j += 8)
        out[(size_t)(yo + j) * K + xo] = __float2half_rn(tile[threadIdx.x][threadIdx.y + j]);
}

// ---------------- LayerNorm: one block per row of 1024 ----------------
template <int HALFOUT>
__global__ __launch_bounds__(256) void ln_kernel(const float* __restrict__ x,
                                                 const float* __restrict__ g,
                                                 const float* __restrict__ be,
                                                 void* __restrict__ out)
{
    int row = blockIdx.x;
    int tid = threadIdx.x;
    const float4* xr = reinterpret_cast<const float4*>(x + (size_t)row * E_);
    float4 a = xr[tid];
    float s  = a.x + a.y + a.z + a.w;
    float ss = a.x * a.x + a.y * a.y + a.z * a.z + a.w * a.w;
#pragma unroll
    for (int o = 16; o > 0; o >>= 1) {
        s  += __shfl_xor_sync(0xffffffffu, s,  o);
        ss += __shfl_xor_sync(0xffffffffu, ss, o);
    }
    __shared__ float sm[8], sm2[8];
    int w = tid >> 5, lane = tid & 31;
    if (lane == 0) { sm[w] = s; sm2[w] = ss; }
    __syncthreads();
    if (tid < 32) {
        s  = (tid < 8) ? sm[tid]  : 0.f;
        ss = (tid < 8) ? sm2[tid] : 0.f;
#pragma unroll
        for (int o = 4; o > 0; o >>= 1) {
            s  += __shfl_xor_sync(0xffffffffu, s,  o);
            ss += __shfl_xor_sync(0xffffffffu, ss, o);
        }
        if (tid == 0) { sm[0] = s; sm2[0] = ss; }
    }
    __syncthreads();
    float mean = sm[0] * (1.0f / E_);
    float var  = sm2[0] * (1.0f / E_) - mean * mean;
    float inv  = rsqrtf(var + 1e-5f);
    float4 gg = reinterpret_cast<const float4*>(g)[tid];
    float4 bb = reinterpret_cast<const float4*>(be)[tid];
    float4 o4;
    o4.x = (a.x - mean) * inv * gg.x + bb.x;
    o4.y = (a.y - mean) * inv * gg.y + bb.y;
    o4.z = (a.z - mean) * inv * gg.z + bb.z;
    o4.w = (a.w - mean) * inv * gg.w + bb.w;
    if (HALFOUT) {
        __half2* op = reinterpret_cast<__half2*>((__half*)out + (size_t)row * E_ + tid * 4);
        op[0] = __floats2half2_rn(o4.x, o4.y);
        op[1] = __floats2half2_rn(o4.z, o4.w);
    } else {
        reinterpret_cast<float4*>((float*)out + (size_t)row * E_)[tid] = o4;
    }
}

// ---------------- QKV projections via fp16 mma, raw f32 weights (ldmatrix.trans B) -----
#define AST 72   // halves; conflict-free for fragment pattern

__global__ __launch_bounds__(128) void qkv_kernel(const __half* __restrict__ nxh,
                                                  const float* __restrict__ Wq,
                                                  const float* __restrict__ Wk,
                                                  const float* __restrict__ Wv,
                                                  __half* __restrict__ q,
                                                  __half* __restrict__ k,
                                                  __half* __restrict__ v)
{
    __shared__ __half Xh[64 * AST];
    __shared__ __half Wh[64 * AST];    // W row-major [k][n], fp16
    int st = blockIdx.x, h = blockIdx.y, b = blockIdx.z;
    int tid  = threadIdx.x;
    int lane = tid & 31, warp = tid >> 5;
    int m0 = warp * 16;
    int r4 = lane >> 2, c4 = lane & 3;

    // ldmatrix.trans per-lane address offsets (B operand from row-major [k][n])
    const int lm = lane >> 3;
    const int lj = lane & 7;
    const int lrow_off = (lm & 1) * 8 + lj;
    const int lcol_off = (lm >> 1) * 8;

#pragma unroll
    for (int it = 0; it < 4; it++) {
        int idx = tid + it * 128;
        int r = idx >> 3, c8 = (idx & 7) * 8;
        uint4 raw = *reinterpret_cast<const uint4*>(
            nxh + ((size_t)(b * S_ + st * 64 + r)) * E_ + h * 64 + c8);
        *reinterpret_cast<uint4*>(Xh + r * AST + c8) = raw;
    }

    const float* Wm[3] = {Wq, Wk, Wv};
    __half*      Om[3] = {q, k, v};
    size_t obase = ((size_t)(b * H_ + h) * S_ + st * 64) * D_;
    uint32_t wbase = (uint32_t)__cvta_generic_to_shared(Wh);

#pragma unroll 1
    for (int m = 0; m < 3; m++) {
        __syncthreads();
        // stage W [64][64] f32 -> fp16 row-major (no transpose)
#pragma unroll
        for (int it = 0; it < 8; it++) {
            int idx = tid + it * 128;               // 1024 float4 chunks
            int r = idx >> 4, cc = (idx & 15) * 4;
            float4 wv4 = *reinterpret_cast<const float4*>(Wm[m] + (size_t)r * 64 + cc);
            uint32_t* wp = reinterpret_cast<uint32_t*>(Wh + r * AST + cc);
            wp[0] = packh2(wv4.x, wv4.y);
            wp[1] = packh2(wv4.z, wv4.w);
        }
        __syncthreads();

        float acc[8][4] = {};
#pragma unroll
        for (int ks = 0; ks < 4; ks++) {
            int kc = ks * 16;
            uint32_t a[4];
            a[0] = *reinterpret_cast<const uint32_t*>(Xh + (m0 + r4) * AST + kc + 2 * c4);
            a[1] = *reinterpret_cast<const uint32_t*>(Xh + (m0 + r4 + 8) * AST + kc + 2 * c4);
            a[2] = *reinterpret_cast<const uint32_t*>(Xh + (m0 + r4) * AST + kc + 2 * c4 + 8);
            a[3] = *reinterpret_cast<const uint32_t*>(Xh + (m0 + r4 + 8) * AST + kc + 2 * c4 + 8);
#pragma unroll
            for (int g = 0; g < 4; g++) {
                uint32_t r[4];
                uint32_t addr = wbase + (uint32_t)(((kc + lrow_off) * AST + g * 16 + lcol_off) * 2);
                ldsm_x4_trans(r, addr);
                uint32_t b0[2] = {r[0], r[1]};
                uint32_t b1[2] = {r[2], r[3]};
                mma_f16(acc[2 * g],     a, b0);
                mma_f16(acc[2 * g + 1], a, b1);
            }
        }
        __half* dst = Om[m] + obase;
#pragma unroll
        for (int ni = 0; ni < 8; ni++) {
            int cc = ni * 8 + 2 * c4;
            *reinterpret_cast<uint32_t*>(dst + (m0 + r4) * D_ + cc)     = packh2(acc[ni][0], acc[ni][1]);
            *reinterpret_cast<uint32_t*>(dst + (m0 + r4 + 8) * D_ + cc) = packh2(acc[ni][2], acc[ni][3]);
        }
    }
}

// ---------------- Causal flash attention: register softmax (__expf), ldmatrix.trans V,
//                  cp.async double-buffered K/V, heaviest-first scheduling ------------
__global__ __launch_bounds__(128) void attn_kernel(const __half* __restrict__ q,
                                                   const __half* __restrict__ k,
                                                   const __half* __restrict__ v,
                                                   __half* __restrict__ o)
{
    __shared__ __half Qh[64 * AST];
    __shared__ __half Kh[2][64 * AST];
    __shared__ __half Vh[2][64 * AST];   // row-major [s][d]

    // heaviest-first: high qt blocks launch first
    int qt = (int)gridDim.x - 1 - (int)blockIdx.x;
    int h = blockIdx.y, b = blockIdx.z;
    int tid  = threadIdx.x;
    int lane = tid & 31, warp = tid >> 5;
    int m0 = warp * 16;
    int r4 = lane >> 2, c4 = lane & 3;
    size_t head_base = (size_t)(b * H_ + h) * S_ * D_;
    const __half2 hscale = __float2half2_rn(0.03125f);  // 1/32 exact

    // ldmatrix.trans per-lane address offsets (within a V tile)
    const int lm = lane >> 3;
    const int lj = lane & 7;
    const int lrow_off = (lm & 1) * 8 + lj;
    const int lcol_off = (lm >> 1) * 8;

    // load Q (scaled)
#pragma unroll
    for (int it = 0; it < 4; it++) {
        int idx = tid + it * 128;
        int r = idx >> 3, c8 = (idx & 7) * 8;
        uint4 raw = *reinterpret_cast<const uint4*>(q + head_base + (size_t)(qt * 64 + r) * 64 + c8);
        __half2* hp = reinterpret_cast<__half2*>(&raw);
#pragma unroll
        for (int j = 0; j < 4; j++) hp[j] = __hmul2(hp[j], hscale);
        *reinterpret_cast<uint4*>(Qh + r * AST + c8) = raw;
    }

    auto stage = [&](int buf, int kt) {
#pragma unroll
        for (int it = 0; it < 4; it++) {
            int idx = tid + it * 128;
            int r = idx >> 3, c8 = (idx & 7) * 8;
            cp_async16(&Kh[buf][r * AST + c8], k + head_base + (size_t)(kt * 64 + r) * 64 + c8);
            cp_async16(&Vh[buf][r * AST + c8], v + head_base + (size_t)(kt * 64 + r) * 64 + c8);
        }
        CP_COMMIT();
    };

    float m_0 = -1e30f, m_1 = -1e30f, l_0 = 0.f, l_1 = 0.f;
    float acc_o[8][4] = {};

    stage(0, 0);

    for (int kt = 0; kt <= qt; kt++) {
        int buf = kt & 1;
        CP_WAIT0();
        __syncthreads();
        if (kt + 1 <= qt) stage(buf ^ 1, kt + 1);

        // ---- S = Q @ K^T : warp computes 16x64 in registers ----
        float s[8][4] = {};
#pragma unroll
        for (int ks = 0; ks < 4; ks++) {
            int kc = ks * 16;
            uint32_t a[4];
            a[0] = *reinterpret_cast<const uint32_t*>(Qh + (m0 + r4) * AST + kc + 2 * c4);
            a[1] = *reinterpret_cast<const uint32_t*>(Qh + (m0 + r4 + 8) * AST + kc + 2 * c4);
            a[2] = *reinterpret_cast<const uint32_t*>(Qh + (m0 + r4) * AST + kc + 2 * c4 + 8);
            a[3] = *reinterpret_cast<const uint32_t*>(Qh + (m0 + r4 + 8) * AST + kc + 2 * c4 + 8);
#pragma unroll
            for (int ni = 0; ni < 8; ni++) {
                int n0 = ni * 8;
                uint32_t bf[2];
                bf[0] = *reinterpret_cast<const uint32_t*>(&Kh[buf][(n0 + r4) * AST + kc + 2 * c4]);
                bf[1] = *reinterpret_cast<const uint32_t*>(&Kh[buf][(n0 + r4) * AST + kc + 2 * c4 + 8]);
                mma_f16(s[ni], a, bf);
            }
        }

        if (kt == qt) {
            int row0 = m0 + r4, row1 = m0 + r4 + 8;
#pragma unroll
            for (int ni = 0; ni < 8; ni++) {
                int col = ni * 8 + 2 * c4;
                if (col > row0)     s[ni][0] = -1e30f;
                if (col + 1 > row0) s[ni][1] = -1e30f;
                if (col > row1)     s[ni][2] = -1e30f;
                if (col + 1 > row1) s[ni][3] = -1e30f;
            }
        }

        // ---- register softmax (__expf: hw ex2.approx) ----
        float mx0 = -1e30f, mx1 = -1e30f;
#pragma unroll
        for (int ni = 0; ni < 8; ni++) {
            mx0 = fmaxf(mx0, fmaxf(s[ni][0], s[ni][1]));
            mx1 = fmaxf(mx1, fmaxf(s[ni][2], s[ni][3]));
        }
        mx0 = fmaxf(mx0, __shfl_xor_sync(0xffffffffu, mx0, 1));
        mx0 = fmaxf(mx0, __shfl_xor_sync(0xffffffffu, mx0, 2));
        mx1 = fmaxf(mx1, __shfl_xor_sync(0xffffffffu, mx1, 1));
        mx1 = fmaxf(mx1, __shfl_xor_sync(0xffffffffu, mx1, 2));

        float mn0 = fmaxf(m_0, mx0), mn1 = fmaxf(m_1, mx1);
        float corr0 = __expf(m_0 - mn0), corr1 = __expf(m_1 - mn1);
        float rs0 = 0.f, rs1 = 0.f;
#pragma unroll
        for (int ni = 0; ni < 8; ni++) {
            s[ni][0] = __expf(s[ni][0] - mn0);
            s[ni][1] = __expf(s[ni][1] - mn0);
            s[ni][2] = __expf(s[ni][2] - mn1);
            s[ni][3] = __expf(s[ni][3] - mn1);
            rs0 += s[ni][0] + s[ni][1];
            rs1 += s[ni][2] + s[ni][3];
        }
        rs0 += __shfl_xor_sync(0xffffffffu, rs0, 1);
        rs0 += __shfl_xor_sync(0xffffffffu, rs0, 2);
        rs1 += __shfl_xor_sync(0xffffffffu, rs1, 1);
        rs1 += __shfl_xor_sync(0xffffffffu, rs1, 2);
        l_0 = l_0 * corr0 + rs0;  m_0 = mn0;
        l_1 = l_1 * corr1 + rs1;  m_1 = mn1;

        // pack P into A-fragments (S C-frag layout == P A-frag layout)
        uint32_t pa[4][4];
#pragma unroll
        for (int kk = 0; kk < 4; kk++) {
            pa[kk][0] = packh2(s[2 * kk][0],     s[2 * kk][1]);
            pa[kk][1] = packh2(s[2 * kk][2],     s[2 * kk][3]);
            pa[kk][2] = packh2(s[2 * kk + 1][0], s[2 * kk + 1][1]);
            pa[kk][3] = packh2(s[2 * kk + 1][2], s[2 * kk + 1][3]);
        }

        // ---- O = O*corr + P @ V  (V B-fragments via ldmatrix.trans) ----
#pragma unroll
        for (int ni = 0; ni < 8; ni++) {
            acc_o[ni][0] *= corr0; acc_o[ni][1] *= corr0;
            acc_o[ni][2] *= corr1; acc_o[ni][3] *= corr1;
        }
        uint32_t vbase = (uint32_t)__cvta_generic_to_shared(&Vh[buf][0]);
#pragma unroll
        for (int kk = 0; kk < 4; kk++) {
            int kc = kk * 16;
#pragma unroll
            for (int g = 0; g < 4; g++) {
                uint32_t r[4];
                uint32_t addr = vbase + (uint32_t)(((kc + lrow_off) * AST + g * 16 + lcol_off) * 2);
                ldsm_x4_trans(r, addr);
                uint32_t b0[2] = {r[0], r[1]};
                uint32_t b1[2] = {r[2], r[3]};
                mma_f16(acc_o[2 * g],     pa[kk], b0);
                mma_f16(acc_o[2 * g + 1], pa[kk], b1);
            }
        }
    }

    // epilogue: normalize, fp16, token-major [B,S,H,D]
    float inv0 = 1.0f / l_0;
    float inv1 = 1.0f / l_1;
    __half* ob = o + ((size_t)(b * S_ + qt * 64)) * E_ + h * 64;
#pragma unroll
    for (int ni = 0; ni < 8; ni++) {
        int cc = ni * 8 + 2 * c4;
        *reinterpret_cast<uint32_t*>(ob + (size_t)(m0 + r4) * E_ + cc) =
            packh2(acc_o[ni][0] * inv0, acc_o[ni][1] * inv0);
        *reinterpret_cast<uint32_t*>(ob + (size_t)(m0 + r4 + 8) * E_ + cc) =
            packh2(acc_o[ni][2] * inv1, acc_o[ni][3] * inv1);
    }
}

// ---------------- FP16 GEMM: 128x256x32 tiles, warp 64x64, 4-stage cp.async ------------
#define BM 128
#define BN 256
#define BKH 32
#define HSTR 40
#define NSTG 4
#define A_STG (BM * HSTR)
#define B_STG (BN * HSTR)
#define GEMM_SMEM_BYTES (NSTG * (A_STG + B_STG) * 2)   // 122880

template <int RELU, int RES, int HALFOUT>
__global__ __launch_bounds__(256) void hgemm_kernel(const __half* __restrict__ A,
                                                    const __half* __restrict__ Bt,
                                                    const float* __restrict__ bias,
                                                    const float* __restrict__ resid,
                                                    void* __restrict__ Cout,
                                                    int M, int N, int K)
{
    extern __shared__ __half shh[];
    __half* Asm = shh;
    __half* Bsm = shh + NSTG * A_STG;

    const int tid  = threadIdx.x;
    const int lane = tid & 31;
    const int warp = tid >> 5;
    const int wm = warp >> 2;
    const int wn = warp & 3;
    const int m_w = wm * 64;
    const int n_w = wn * 64;
    const int r4 = lane >> 2;
    const int c4 = lane & 3;
    const int bx = blockIdx.x, by = blockIdx.y;

    const __half* Ab = A  + (size_t)by * BM * K;
    const __half* Bb = Bt + (size_t)bx * BN * K;

    auto load_tile = [&](int buf, int k0) {
        __half* Ad = Asm + buf * A_STG;
        __half* Bd = Bsm + buf * B_STG;
#pragma unroll
        for (int i = 0; i < 2; i++) {
            int idx = tid + i * 256;
            int row = idx >> 2, kq = (idx & 3) * 8;
            cp_async16(Ad + row * HSTR + kq, Ab + (size_t)row * K + k0 + kq);
        }
#pragma unroll
        for (int i = 0; i < 4; i++) {
            int idx = tid + i * 256;
            int row = idx >> 2, kq = (idx & 3) * 8;
            cp_async16(Bd + row * HSTR + kq, Bb + (size_t)row * K + k0 + kq);
        }
        CP_COMMIT();
    };

    float acc[4][8][4] = {};

    const int nT = K / BKH;
    load_tile(0, 0);
    load_tile(1, BKH);
    load_tile(2, 2 * BKH);

#pragma unroll 1
    for (int t = 0; t < nT; t++) {
        int pend = nT - 1 - t;
        if (pend >= 2)      { CP_WAIT2(); }
        else if (pend == 1) { CP_WAIT1(); }
        else                { CP_WAIT0(); }
        __syncthreads();
        if (t + 3 < nT) load_tile((t + 3) % NSTG, (t + 3) * BKH);

        const __half* Ac = Asm + (t % NSTG) * A_STG;
        const __half* Bc = Bsm + (t % NSTG) * B_STG;
#pragma unroll
        for (int ks = 0; ks < 2; ks++) {
            const int kc = ks * 16;
            uint32_t a[4][4], b[8][2];
#pragma unroll
            for (int mi = 0; mi < 4; mi++) {
                int m0 = m_w + mi * 16;
                a[mi][0] = *reinterpret_cast<const uint32_t*>(Ac + (m0 + r4) * HSTR + kc + 2 * c4);
                a[mi][1] = *reinterpret_cast<const uint32_t*>(Ac + (m0 + r4 + 8) * HSTR + kc + 2 * c4);
                a[mi][2] = *reinterpret_cast<const uint32_t*>(Ac + (m0 + r4) * HSTR + kc + 2 * c4 + 8);
                a[mi][3] = *reinterpret_cast<const uint32_t*>(Ac + (m0 + r4 + 8) * HSTR + kc + 2 * c4 + 8);
            }
#pragma unroll
            for (int ni = 0; ni < 8; ni++) {
                int n0 = n_w + ni * 8;
                b[ni][0] = *reinterpret_cast<const uint32_t*>(Bc + (n0 + r4) * HSTR + kc + 2 * c4);
                b[ni][1] = *reinterpret_cast<const uint32_t*>(Bc + (n0 + r4) * HSTR + kc + 2 * c4 + 8);
            }
#pragma unroll
            for (int mi = 0; mi < 4; mi++)
#pragma unroll
                for (int ni = 0; ni < 8; ni++)
                    mma_f16(acc[mi][ni], a[mi], b[ni]);
        }
    }

    const int row_base = by * BM + m_w;
    const int col_base = bx * BN + n_w;
#pragma unroll
    for (int mi = 0; mi < 4; mi++) {
#pragma unroll
        for (int ni = 0; ni < 8; ni++) {
            int c0 = col_base + ni * 8 + 2 * c4;
            float2 bb = *reinterpret_cast<const float2*>(bias + c0);
#pragma unroll
            for (int half = 0; half < 2; half++) {
                int r0 = row_base + mi * 16 + r4 + half * 8;
                float v0 = acc[mi][ni][half * 2]     + bb.x;
                float v1 = acc[mi][ni][half * 2 + 1] + bb.y;
                if (RELU) { v0 = fmaxf(v0, 0.f); v1 = fmaxf(v1, 0.f); }
                if (RES) {
                    float2 rr = *reinterpret_cast<const float2*>(resid + (size_t)r0 * N + c0);
                    v0 += rr.x; v1 += rr.y;
                }
                if (HALFOUT) {
                    *reinterpret_cast<__half2*>((__half*)Cout + (size_t)r0 * N + c0) =
                        __floats2half2_rn(v0, v1);
                } else {
                    float2 o2 = {v0, v1};
                    *reinterpret_cast<float2*>((float*)Cout + (size_t)r0 * N + c0) = o2;
                }
            }
        }
    }
}

// ---------------- launch ----------------
extern "C" void kernel_launch(void* const* d_in, const int* in_sizes, int n_in,
                              void* d_out, int out_size)
{
    (void)in_sizes; (void)n_in; (void)out_size;
    const float* x   = (const float*)d_in[0];
    const float* Wq  = (const float*)d_in[1];
    const float* Wk  = (const float*)d_in[2];
    const float* Wv  = (const float*)d_in[3];
    const float* Wo  = (const float*)d_in[4];
    const float* bo  = (const float*)d_in[5];
    const float* W1  = (const float*)d_in[6];
    const float* b1  = (const float*)d_in[7];
    const float* W2  = (const float*)d_in[8];
    const float* b2  = (const float*)d_in[9];
    const float* g1  = (const float*)d_in[10];
    const float* be1 = (const float*)d_in[11];
    const float* g2  = (const float*)d_in[12];
    const float* be2 = (const float*)d_in[13];
    float* out = (float*)d_out;

    float *x1;
    __half *nxh, *qb, *kb, *vb, *ob, *nx2, *h1, *woT, *w1T, *w2T;
    cudaGetSymbolAddress((void**)&nxh, g_nxh);
    cudaGetSymbolAddress((void**)&qb,  g_q);
    cudaGetSymbolAddress((void**)&kb,  g_k);
    cudaGetSymbolAddress((void**)&vb,  g_v);
    cudaGetSymbolAddress((void**)&ob,  g_o);
    cudaGetSymbolAddress((void**)&x1,  g_x1);
    cudaGetSymbolAddress((void**)&nx2, g_nx2);
    cudaGetSymbolAddress((void**)&h1,  g_h1);
    cudaGetSymbolAddress((void**)&woT, g_woT);
    cudaGetSymbolAddress((void**)&w1T, g_w1T);
    cudaGetSymbolAddress((void**)&w2T, g_w2T);

    cudaFuncSetAttribute(hgemm_kernel<0, 1, 0>, cudaFuncAttributeMaxDynamicSharedMemorySize,
                         GEMM_SMEM_BYTES);
    cudaFuncSetAttribute(hgemm_kernel<1, 0, 1>, cudaFuncAttributeMaxDynamicSharedMemorySize,
                         GEMM_SMEM_BYTES);

    // fork a side stream (capture-legal): big weight transposes run concurrently
    // with the LN1 -> QKV -> attention chain; join before the Wo GEMM.
    cudaStream_t s2 = 0;
    cudaEvent_t evFork = 0, evJoin = 0;
    bool forked = false;
    if (cudaStreamCreateWithFlags(&s2, cudaStreamNonBlocking) == cudaSuccess &&
        cudaEventCreateWithFlags(&evFork, cudaEventDisableTiming) == cudaSuccess &&
        cudaEventCreateWithFlags(&evJoin, cudaEventDisableTiming) == cudaSuccess) {
        forked = (cudaEventRecord(evFork, 0) == cudaSuccess) &&
                 (cudaStreamWaitEvent(s2, evFork, 0) == cudaSuccess);
    }
    cudaStream_t ts = forked ? s2 : 0;

    // 0) big weight transposes (side stream if forked)
    transpose_h_kernel<<<dim3(E_ / 32, E_ / 32), dim3(32, 8), 0, ts>>>(Wo, woT, E_, E_);
    transpose_h_kernel<<<dim3(F_ / 32, E_ / 32), dim3(32, 8), 0, ts>>>(W1, w1T, E_, F_);
    transpose_h_kernel<<<dim3(E_ / 32, F_ / 32), dim3(32, 8), 0, ts>>>(W2, w2T, F_, E_);
    if (forked) {
        cudaEventRecord(evJoin, s2);
    }

    // 1) LN1 (fp16 out)
    ln_kernel<1><<<TOK, 256>>>(x, g1, be1, nxh);
    // 2) QKV projections (fp16 mma, raw f32 weights staged in-kernel)
    qkv_kernel<<<dim3(S_ / 64, H_, B_), 128>>>(nxh, Wq, Wk, Wv, qb, kb, vb);
    // 3) causal flash attention -> o fp16
    attn_kernel<<<dim3(S_ / 64, H_, B_), 128>>>(qb, kb, vb, ob);

    // join: Wo/W1/W2 transposes must be done before the GEMMs
    if (forked) {
        cudaStreamWaitEvent(0, evJoin, 0);
    }

    // 4) x1 = x + o @ Wo + bo   (f32 out)
    hgemm_kernel<0, 1, 0><<<dim3(E_ / BN, TOK / BM), 256, GEMM_SMEM_BYTES>>>(ob, woT, bo, x, x1, TOK, E_, E_);
    // 5) LN2 (fp16 out)
    ln_kernel<1><<<TOK, 256>>>(x1, g2, be2, nx2);
    // 6) h1 = relu(nx2 @ W1 + b1)  (fp16 out)
    hgemm_kernel<1, 0, 1><<<dim3(F_ / BN, TOK / BM), 256, GEMM_SMEM_BYTES>>>(nx2, w1T, b1, nullptr, h1, TOK, F_, E_);
    // 7) out = x1 + h1 @ W2 + b2   (f32 out)
    hgemm_kernel<0, 1, 0><<<dim3(E_ / BN, TOK / BM), 256, GEMM_SMEM_BYTES>>>(h1, w2T, b2, x1, out, TOK, E_, F_);
    // note: s2/evFork/evJoin intentionally not destroyed — handles are tiny,
    // kernel_launch is called only a few times, and destroying mid-capture is risky.
}